// round 5
// baseline (speedup 1.0000x reference)
#include <cuda_runtime.h>
#include <cuda_fp16.h>

#define BB 16
#define MM 2048
#define NN 2048
#define GRP 8            // batches per group (group K slice = 67 MB < L2)
#define R  8             // rows per CTA in the iteration kernel
#define NITER 100

// Scratch (static __device__ globals -- no runtime allocation)
__device__ __half g_K[(size_t)BB * MM * NN];   // 134 MB fp16 kernel matrix
__device__ float  g_T[3][BB * NN];             // triple-buffered column sums
__device__ float  g_z[BB * MM];                // current z = exp(u)

struct alignas(8) Half4 { __half2 a, b; };

// ---------------------------------------------------------------------------
// K = exp(-C / eps) = exp(-10 C), stored fp16. One float4 per thread.
// ---------------------------------------------------------------------------
__global__ void build_K_kernel(const float* __restrict__ C) {
    size_t i = (size_t)blockIdx.x * blockDim.x + threadIdx.x;   // float4 index
    float4 c = ((const float4*)C)[i];
    __half2 h01 = __floats2half2_rn(__expf(-10.f * c.x), __expf(-10.f * c.y));
    __half2 h23 = __floats2half2_rn(__expf(-10.f * c.z), __expf(-10.f * c.w));
    Half4 o; o.a = h01; o.b = h23;
    ((Half4*)g_K)[i] = o;
}

// ---------------------------------------------------------------------------
// T[0] = b  (so the first iteration sees w = b/T = 1, matching v0 = 0),
// T[1] = T[2] = 0, distance accumulators = 0.
// ---------------------------------------------------------------------------
__global__ void init_kernel(const float* __restrict__ b, float* __restrict__ out) {
    int i = blockIdx.x * blockDim.x + threadIdx.x;   // < BB*NN = 32768
    float bv = b[i];
    g_T[0][i] = bv;
    g_T[1][i] = 0.f;
    g_T[2][i] = 0.f;
    if (i < BB) out[i] = 0.f;
}

// ---------------------------------------------------------------------------
// One Sinkhorn iteration for an 8-batch GROUP (K slice is L2-resident).
// Thread t owns 4 contiguous columns [4t, 4t+4); CTA covers 8 rows.
//   phase 1: per-row 4-col dot -> 4-lane shfl pre-reduce -> part[8][128]
//            -> one warp per row: 4 LDS + 5 shfl -> z_i = a_i / S_i
//   phase 2: acc_j += K_ij * z_i from the SAME registers (K read once/iter)
//   final:   one red.global.add.v4.f32 per thread into T_out
// Also zeroes its slice of T[zeroIdx] (needed two iterations later).
// Grid: (MM/R, GRP) = (256, 8); 512 threads; 3 CTAs/SM.
// ---------------------------------------------------------------------------
__global__ void __launch_bounds__(512, 3)
sinkhorn_iter(const float* __restrict__ a, const float* __restrict__ b,
              int batch0, int inIdx, int outIdx, int zeroIdx) {
    __shared__ float part[R * 128];  // pre-reduced partials, 4 KB
    __shared__ float zs[R];

    const int batch = batch0 + blockIdx.y;
    const int rb    = blockIdx.x;
    const int tid   = threadIdx.x;
    const int warp  = tid >> 5, lane = tid & 31;
    const int row0  = rb * R;

    // w for this thread's 4 contiguous columns
    const float4* b4 = (const float4*)(b + batch * NN);
    const float4* t4 = (const float4*)(g_T[inIdx] + batch * NN);
    float4 bv = b4[tid];
    float4 tv = t4[tid];
    const float w0 = __fdividef(bv.x, tv.x);
    const float w1 = __fdividef(bv.y, tv.y);
    const float w2 = __fdividef(bv.z, tv.z);
    const float w3 = __fdividef(bv.w, tv.w);

    // Zero slice of the buffer used two iterations from now (2048/256 = 8/CTA)
    if (tid < 8) g_T[zeroIdx][batch * NN + rb * 8 + tid] = 0.f;

    // Register tile: 8 rows x 4 fp16 cols, one coalesced LDG.64 per row
    uint2 tile[R];
    const uint2* src = (const uint2*)(g_K + ((size_t)batch * MM + row0) * NN);
    #pragma unroll
    for (int i = 0; i < R; i++)
        tile[i] = src[i * (NN / 4) + tid];

    // Phase 1: per-row dots, 4-lane pre-reduce, store 1 partial per 4 lanes
    #pragma unroll
    for (int i = 0; i < R; i++) {
        float2 f0 = __half22float2(*(const __half2*)&tile[i].x);
        float2 f1 = __half22float2(*(const __half2*)&tile[i].y);
        float v = f0.x * w0 + f0.y * w1 + f1.x * w2 + f1.y * w3;
        v += __shfl_xor_sync(0xffffffffu, v, 1);
        v += __shfl_xor_sync(0xffffffffu, v, 2);
        if ((lane & 3) == 0) part[i * 128 + (tid >> 2)] = v;
    }
    __syncthreads();

    // One warp per row: 128 partials -> row sum -> z
    if (warp < R) {
        const float* p = &part[warp * 128 + lane];
        float s = p[0] + p[32] + p[64] + p[96];
        s += __shfl_xor_sync(0xffffffffu, s, 16);
        s += __shfl_xor_sync(0xffffffffu, s, 8);
        s += __shfl_xor_sync(0xffffffffu, s, 4);
        s += __shfl_xor_sync(0xffffffffu, s, 2);
        s += __shfl_xor_sync(0xffffffffu, s, 1);
        if (lane == 0) {
            int   ri = batch * MM + row0 + warp;
            float zi = __fdividef(__ldg(&a[ri]), s);
            zs[warp] = zi;
            g_z[ri]  = zi;
        }
    }
    __syncthreads();

    // Phase 2: column partials from the same registers
    float a0 = 0.f, a1 = 0.f, a2 = 0.f, a3 = 0.f;
    #pragma unroll
    for (int i = 0; i < R; i++) {
        float zi = zs[i];
        float2 f0 = __half22float2(*(const __half2*)&tile[i].x);
        float2 f1 = __half22float2(*(const __half2*)&tile[i].y);
        a0 += f0.x * zi; a1 += f0.y * zi;
        a2 += f1.x * zi; a3 += f1.y * zi;
    }

    // One vector reduction per thread (16B-aligned)
    float* To = g_T[outIdx] + batch * NN + 4 * tid;
    asm volatile("red.global.add.v4.f32 [%0], {%1, %2, %3, %4};"
                 :: "l"(To), "f"(a0), "f"(a1), "f"(a2), "f"(a3)
                 : "memory");
}

// ---------------------------------------------------------------------------
// P_ij = z_i * exp(-10 C_ij) * w_j  (exact fp32 K for the output),
// distance_b = sum_ij P_ij C_ij.
// Grid: (MM/8, BB); 256 threads; each CTA does 8 rows x 2048 cols.
// ---------------------------------------------------------------------------
__global__ void __launch_bounds__(256)
finalize_kernel(const float* __restrict__ C, const float* __restrict__ b,
                float* __restrict__ out, int tIdx) {
    const int batch = blockIdx.y;
    const int rb    = blockIdx.x;
    const int tid   = threadIdx.x;

    const float4* b4 = (const float4*)(b + batch * NN);
    const float4* t4 = (const float4*)(g_T[tIdx] + batch * NN);
    float4 bv0 = b4[tid], bv1 = b4[tid + 256];
    float4 tv0 = t4[tid], tv1 = t4[tid + 256];
    float4 w0 = make_float4(bv0.x / tv0.x, bv0.y / tv0.y, bv0.z / tv0.z, bv0.w / tv0.w);
    float4 w1 = make_float4(bv1.x / tv1.x, bv1.y / tv1.y, bv1.z / tv1.z, bv1.w / tv1.w);

    const size_t rowbase = (size_t)batch * MM + rb * 8;
    float* P = out + BB;
    float acc = 0.f;

    #pragma unroll
    for (int i = 0; i < 8; i++) {
        float zi = g_z[rowbase + i];
        const float4* Crow = (const float4*)(C + (rowbase + i) * NN);
        float4 c0 = Crow[tid], c1 = Crow[tid + 256];
        float4 p0, p1;
        p0.x = zi * __expf(-10.f * c0.x) * w0.x;
        p0.y = zi * __expf(-10.f * c0.y) * w0.y;
        p0.z = zi * __expf(-10.f * c0.z) * w0.z;
        p0.w = zi * __expf(-10.f * c0.w) * w0.w;
        p1.x = zi * __expf(-10.f * c1.x) * w1.x;
        p1.y = zi * __expf(-10.f * c1.y) * w1.y;
        p1.z = zi * __expf(-10.f * c1.z) * w1.z;
        p1.w = zi * __expf(-10.f * c1.w) * w1.w;
        float4* Prow = (float4*)(P + (rowbase + i) * NN);
        Prow[tid]       = p0;
        Prow[tid + 256] = p1;
        acc += p0.x * c0.x + p0.y * c0.y + p0.z * c0.z + p0.w * c0.w
             + p1.x * c1.x + p1.y * c1.y + p1.z * c1.z + p1.w * c1.w;
    }

    // Block-reduce distance partial, one atomic per CTA per batch
    #pragma unroll
    for (int off = 16; off; off >>= 1)
        acc += __shfl_xor_sync(0xffffffffu, acc, off);
    __shared__ float rbuf[8];
    int warp = tid >> 5, lane = tid & 31;
    if (lane == 0) rbuf[warp] = acc;
    __syncthreads();
    if (tid == 0) {
        float s = 0.f;
        #pragma unroll
        for (int k = 0; k < 8; k++) s += rbuf[k];
        atomicAdd(&out[batch], s);
    }
}

// ---------------------------------------------------------------------------
extern "C" void kernel_launch(void* const* d_in, const int* in_sizes, int n_in,
                              void* d_out, int out_size) {
    const float* C = (const float*)d_in[0];   // (16, 2048, 2048)
    const float* a = (const float*)d_in[1];   // (16, 2048)
    const float* b = (const float*)d_in[2];   // (16, 2048)
    float* out = (float*)d_out;               // [0..16) distance, [16..) P

    // 16*2048*2048 / 4 float4s / 256 threads = 65536 blocks (exact)
    build_K_kernel<<<65536, 256>>>(C);
    init_kernel<<<(BB * NN) / 256, 256>>>(b, out);

    // Process batch groups sequentially so each group's 67 MB K slice stays
    // L2-resident across its 100 iterations (batches are independent).
    for (int g = 0; g < BB / GRP; g++) {
        for (int k = 0; k < NITER; k++) {
            sinkhorn_iter<<<dim3(MM / R, GRP), 512>>>(
                a, b, g * GRP, k % 3, (k + 1) % 3, (k + 2) % 3);
        }
    }

    finalize_kernel<<<dim3(MM / 8, BB), 256>>>(C, b, out, NITER % 3);
}